// round 12
// baseline (speedup 1.0000x reference)
#include <cuda_runtime.h>
#include <cstdint>

#define NN 50000
#define NE 800000
#define DD 128
#define NBLK 196   // ceil(50000/256)

// ------------------------- device scratch (no allocs) -----------------------
__device__ float  g_accum[NN * DD];  // aggregated messages (sum)
__device__ float  g_cnt[NN];         // in-degree (float, for GEMM1 fusion)
__device__ float  g_h[NN * DD];      // after GEMM1 + relu
__device__ int    g_deg[NN];
__device__ int    g_off[NN];         // exclusive offsets
__device__ int    g_wptr[NN];        // fill cursors (init = g_off)
__device__ float2 g_edges[NE];       // (src as int-bits, attr) in CSR order
__device__ int    g_bsum[NBLK];
__device__ int    g_boff[NBLK];

// ---- packed f32x2 helpers (base PTX ISA, sm_100+; not 'a'-gated) -----------
__device__ __forceinline__ unsigned long long pack2(float lo, float hi) {
    unsigned long long r;
    asm("mov.b64 %0, {%1, %2};" : "=l"(r) : "f"(lo), "f"(hi));
    return r;
}
__device__ __forceinline__ void unpack2(float& lo, float& hi, unsigned long long v) {
    asm("mov.b64 {%0, %1}, %2;" : "=f"(lo), "=f"(hi) : "l"(v));
}
__device__ __forceinline__ void ffma2(unsigned long long& d, unsigned long long a,
                                      unsigned long long b) {
    asm("fma.rn.f32x2 %0, %1, %2, %0;" : "+l"(d) : "l"(a), "l"(b));
}

// ---------------------------------------------------------------------------
// CSR build
// ---------------------------------------------------------------------------
__global__ void zero_deg_kernel() {
    int i = blockIdx.x * blockDim.x + threadIdx.x;
    if (i < NN) g_deg[i] = 0;
}

__global__ void hist_kernel(const int* __restrict__ edge_index) {
    int e = blockIdx.x * blockDim.x + threadIdx.x;
    if (e < NE) atomicAdd(&g_deg[__ldg(&edge_index[NE + e])], 1);
}

__global__ void bsum_kernel() {
    __shared__ int s[256];
    int t = threadIdx.x;
    int i = blockIdx.x * 256 + t;
    s[t] = (i < NN) ? g_deg[i] : 0;
    __syncthreads();
    for (int off = 128; off > 0; off >>= 1) {
        if (t < off) s[t] += s[t + off];
        __syncthreads();
    }
    if (t == 0) g_bsum[blockIdx.x] = s[0];
}

__global__ void scan_bsum_kernel() {
    __shared__ int s[256];
    int t = threadIdx.x;
    int v = (t < NBLK) ? g_bsum[t] : 0;
    s[t] = v;
    __syncthreads();
    for (int off = 1; off < 256; off <<= 1) {
        int x = (t >= off) ? s[t - off] : 0;
        __syncthreads();
        s[t] += x;
        __syncthreads();
    }
    if (t < NBLK) g_boff[t] = s[t] - v;
}

__global__ void block_scan_kernel() {
    __shared__ int s[256];
    int t = threadIdx.x;
    int i = blockIdx.x * 256 + t;
    int v = (i < NN) ? g_deg[i] : 0;
    s[t] = v;
    __syncthreads();
    for (int off = 1; off < 256; off <<= 1) {
        int x = (t >= off) ? s[t - off] : 0;
        __syncthreads();
        s[t] += x;
        __syncthreads();
    }
    if (i < NN) {
        int excl = s[t] - v + g_boff[blockIdx.x];
        g_off[i]  = excl;
        g_wptr[i] = excl;
    }
}

__global__ void fill_kernel(const int* __restrict__ edge_index,
                            const float* __restrict__ edge_attr) {
    int e = blockIdx.x * blockDim.x + threadIdx.x;
    if (e < NE) {
        int dst = __ldg(&edge_index[NE + e]);
        int src = __ldg(&edge_index[e]);
        float a = __ldg(&edge_attr[e]);
        int pos = atomicAdd(&g_wptr[dst], 1);
        g_edges[pos] = make_float2(__int_as_float(src), a);
    }
}

// ---------------------------------------------------------------------------
// Gather: one warp per dst node; prefetch-4 ring over packed edges (4 hidden
// loads in flight).
// ---------------------------------------------------------------------------
__global__ void gather_kernel(const float* __restrict__ hidden,
                              const float* __restrict__ We,
                              const float* __restrict__ be) {
    int gtid = blockIdx.x * blockDim.x + threadIdx.x;
    int n = gtid >> 5, lane = gtid & 31;
    if (n >= NN) return;

    int deg  = g_deg[n];
    int base = g_off[n];
    int d0   = lane * 4;

    float4 w = *(const float4*)&We[d0];
    float4 b = *(const float4*)&be[d0];
    float4 acc = make_float4(0.f, 0.f, 0.f, 0.f);

    int   sbuf[4] = {0, 0, 0, 0};
    float abuf[4] = {0.f, 0.f, 0.f, 0.f};
#pragma unroll
    for (int p = 0; p < 4; p++) {
        if (p < deg) {
            float2 ed = __ldg(&g_edges[base + p]);
            sbuf[p] = __float_as_int(ed.x);
            abuf[p] = ed.y;
        }
    }

    for (int j = 0; j < deg; j++) {
        int   src = sbuf[j & 3];
        float a   = abuf[j & 3];
        float4 h  = *(const float4*)&hidden[(size_t)src * DD + d0];
        if (j + 4 < deg) {
            float2 ed = __ldg(&g_edges[base + j + 4]);
            sbuf[j & 3] = __float_as_int(ed.x);
            abuf[j & 3] = ed.y;
        }
        acc.x += fmaxf(fmaf(a, w.x, b.x) + h.x, 0.f);
        acc.y += fmaxf(fmaf(a, w.y, b.y) + h.y, 0.f);
        acc.z += fmaxf(fmaf(a, w.z, b.z) + h.z, 0.f);
        acc.w += fmaxf(fmaf(a, w.w, b.w) + h.w, 0.f);
    }

    *(float4*)&g_accum[(size_t)n * DD + d0] = acc;
    if (lane == 0) g_cnt[n] = (float)deg;
}

// ---------------------------------------------------------------------------
// GEMMs: full-K tiles in dynamic smem (A 64x128 k-major + W 128x128 = 97KB),
// ONE barrier, then uninterrupted 128-deep FFMA2 loop. 4 f32x2 row-pairs x
// 4 cols per thread. FUSED finalize in A loader.
// ---------------------------------------------------------------------------
#define A_STRIDE 66
#define SM_BYTES ((128 * A_STRIDE + 128 * 128) * 4)

template <bool FUSED, bool RELU>
__global__ __launch_bounds__(256, 2)
void gemm128_kernel(const float* __restrict__ Ain,
                    const float* __restrict__ eps,
                    const float* __restrict__ W,
                    const float* __restrict__ bias,
                    float* __restrict__ C, int M) {
    extern __shared__ float sm[];
    float* As2 = sm;                    // [128 k][66]   (64 rows used)
    float* Ws  = sm + 128 * A_STRIDE;   // [128 k][128]

    int tid  = threadIdx.x;
    int warp = tid >> 5;
    int lane = tid & 31;
    int row0 = blockIdx.x * 64;
    int r0   = warp * 8;
    int c0   = lane * 4;

    float s = FUSED ? (1.0f + __ldg(&eps[0])) : 0.f;

    // A tile: 64 rows x 128 k = 2048 float4, transposed store
#pragma unroll
    for (int idx = tid; idx < 2048; idx += 256) {
        int r = idx >> 5, f = idx & 31;
        int grow = row0 + r;
        float4 v = make_float4(0.f, 0.f, 0.f, 0.f);
        if (grow < M) {
            size_t off = (size_t)grow * DD + f * 4;
            v = *(const float4*)&Ain[off];
            if (FUSED) {
                float inv = 1.0f / fmaxf(g_cnt[grow], 1.0f);
                float4 a = *(const float4*)&g_accum[off];
                v.x = fmaf(s, v.x, a.x * inv);
                v.y = fmaf(s, v.y, a.y * inv);
                v.z = fmaf(s, v.z, a.z * inv);
                v.w = fmaf(s, v.w, a.w * inv);
            }
        }
        As2[(f * 4 + 0) * A_STRIDE + r] = v.x;
        As2[(f * 4 + 1) * A_STRIDE + r] = v.y;
        As2[(f * 4 + 2) * A_STRIDE + r] = v.z;
        As2[(f * 4 + 3) * A_STRIDE + r] = v.w;
    }
    // W tile: 128 k-rows x 128 cols = 4096 float4
#pragma unroll
    for (int idx = tid; idx < 4096; idx += 256) {
        int r = idx >> 5, f = idx & 31;
        *(float4*)&Ws[r * DD + f * 4] = *(const float4*)&W[(size_t)r * DD + f * 4];
    }
    __syncthreads();

    unsigned long long acc[4][4];
#pragma unroll
    for (int p = 0; p < 4; p++)
#pragma unroll
        for (int c = 0; c < 4; c++) acc[p][c] = 0ull;

#pragma unroll 8
    for (int kk = 0; kk < 128; kk++) {
        float4 bv = *(float4*)&Ws[kk * DD + c0];
        unsigned long long bb[4];
        bb[0] = pack2(bv.x, bv.x);
        bb[1] = pack2(bv.y, bv.y);
        bb[2] = pack2(bv.z, bv.z);
        bb[3] = pack2(bv.w, bv.w);
        const float* arow = &As2[kk * A_STRIDE + r0];
#pragma unroll
        for (int p = 0; p < 4; p++) {
            unsigned long long a2 = *(const unsigned long long*)&arow[2 * p];
            ffma2(acc[p][0], a2, bb[0]);
            ffma2(acc[p][1], a2, bb[1]);
            ffma2(acc[p][2], a2, bb[2]);
            ffma2(acc[p][3], a2, bb[3]);
        }
    }

    float4 bb4 = *(const float4*)&bias[c0];
#pragma unroll
    for (int p = 0; p < 4; p++) {
        float lo[4], hi[4];
#pragma unroll
        for (int c = 0; c < 4; c++) unpack2(lo[c], hi[c], acc[p][c]);

        int rA = row0 + r0 + 2 * p;
        if (rA < M) {
            float4 o;
            o.x = lo[0] + bb4.x; o.y = lo[1] + bb4.y;
            o.z = lo[2] + bb4.z; o.w = lo[3] + bb4.w;
            if (RELU) {
                o.x = fmaxf(o.x, 0.f); o.y = fmaxf(o.y, 0.f);
                o.z = fmaxf(o.z, 0.f); o.w = fmaxf(o.w, 0.f);
            }
            *(float4*)&C[(size_t)rA * DD + c0] = o;
        }
        int rB = rA + 1;
        if (rB < M) {
            float4 o;
            o.x = hi[0] + bb4.x; o.y = hi[1] + bb4.y;
            o.z = hi[2] + bb4.z; o.w = hi[3] + bb4.w;
            if (RELU) {
                o.x = fmaxf(o.x, 0.f); o.y = fmaxf(o.y, 0.f);
                o.z = fmaxf(o.z, 0.f); o.w = fmaxf(o.w, 0.f);
            }
            *(float4*)&C[(size_t)rB * DD + c0] = o;
        }
    }
}

// ---------------------------------------------------------------------------
extern "C" void kernel_launch(void* const* d_in, const int* in_sizes, int n_in,
                              void* d_out, int out_size) {
    const float* hidden = (const float*)d_in[0];
    const int*   eidx   = (const int*)d_in[1];
    const float* eattr  = (const float*)d_in[2];
    const float* We     = (const float*)d_in[3];
    const float* be     = (const float*)d_in[4];
    const float* W1     = (const float*)d_in[5];
    const float* b1     = (const float*)d_in[6];
    const float* W2     = (const float*)d_in[7];
    const float* b2     = (const float*)d_in[8];
    const float* eps    = (const float*)d_in[9];
    float*       out    = (float*)d_out;

    // DEVICE address of g_h (host &g_h is the ATS-readable shadow symbol!)
    float* p_h = nullptr;
    cudaGetSymbolAddress((void**)&p_h, g_h);

    cudaFuncSetAttribute(gemm128_kernel<true,  true >,
                         cudaFuncAttributeMaxDynamicSharedMemorySize, SM_BYTES);
    cudaFuncSetAttribute(gemm128_kernel<false, false>,
                         cudaFuncAttributeMaxDynamicSharedMemorySize, SM_BYTES);

    // --- CSR build ---
    zero_deg_kernel<<<NBLK, 256>>>();
    hist_kernel<<<(NE + 255) / 256, 256>>>(eidx);
    bsum_kernel<<<NBLK, 256>>>();
    scan_bsum_kernel<<<1, 256>>>();
    block_scan_kernel<<<NBLK, 256>>>();
    fill_kernel<<<(NE + 255) / 256, 256>>>(eidx, eattr);

    // --- gather (no float atomics) ---
    gather_kernel<<<(NN * 32 + 255) / 256, 256>>>(hidden, We, be);

    // --- MLP ---
    int gblocks = (NN + 63) / 64;   // 782
    gemm128_kernel<true,  true ><<<gblocks, 256, SM_BYTES>>>(hidden, eps, W1, b1, p_h, NN);
    gemm128_kernel<false, false><<<gblocks, 256, SM_BYTES>>>(p_h,    eps, W2, b2, out, NN);
}

// round 13
// speedup vs baseline: 1.2218x; 1.2218x over previous
#include <cuda_runtime.h>
#include <cstdint>

#define NN 50000
#define NE 800000
#define DD 128
#define NBLK 196   // ceil(50000/256)

// ------------------------- device scratch (no allocs) -----------------------
__device__ float  g_accum[NN * DD];  // aggregated messages (sum)
__device__ float  g_cnt[NN];         // in-degree (float, for GEMM1 fusion)
__device__ float  g_h[NN * DD];      // after GEMM1 + relu
__device__ int    g_deg[NN];
__device__ int    g_off[NN];         // exclusive offsets
__device__ int    g_wptr[NN];        // fill cursors (init = g_off)
__device__ float2 g_edges[NE];       // (src as int-bits, attr) in CSR order
__device__ int    g_bsum[NBLK];
__device__ int    g_boff[NBLK];

__device__ __forceinline__ uint32_t f2tf32(float x) {
    uint32_t r;
    asm("cvt.rna.tf32.f32 %0, %1;" : "=r"(r) : "f"(x));
    return r;
}
// m16n8k8 tf32 MMA, fp32 accumulate (base PTX, sm_80+, NOT 'a'-gated)
__device__ __forceinline__ void mma1688(float* c, const uint32_t* a,
                                        uint32_t b0, uint32_t b1) {
    asm("mma.sync.aligned.m16n8k8.row.col.f32.tf32.tf32.f32 "
        "{%0,%1,%2,%3},{%4,%5,%6,%7},{%8,%9},{%0,%1,%2,%3};"
        : "+f"(c[0]), "+f"(c[1]), "+f"(c[2]), "+f"(c[3])
        : "r"(a[0]), "r"(a[1]), "r"(a[2]), "r"(a[3]), "r"(b0), "r"(b1));
}

// ---------------------------------------------------------------------------
// CSR build
// ---------------------------------------------------------------------------
__global__ void zero_deg_kernel() {
    int i = blockIdx.x * blockDim.x + threadIdx.x;
    if (i < NN) g_deg[i] = 0;
}

__global__ void hist_kernel(const int* __restrict__ edge_index) {
    int e = blockIdx.x * blockDim.x + threadIdx.x;
    if (e < NE) atomicAdd(&g_deg[__ldg(&edge_index[NE + e])], 1);
}

__global__ void bsum_kernel() {
    __shared__ int s[256];
    int t = threadIdx.x;
    int i = blockIdx.x * 256 + t;
    s[t] = (i < NN) ? g_deg[i] : 0;
    __syncthreads();
    for (int off = 128; off > 0; off >>= 1) {
        if (t < off) s[t] += s[t + off];
        __syncthreads();
    }
    if (t == 0) g_bsum[blockIdx.x] = s[0];
}

__global__ void scan_bsum_kernel() {
    __shared__ int s[256];
    int t = threadIdx.x;
    int v = (t < NBLK) ? g_bsum[t] : 0;
    s[t] = v;
    __syncthreads();
    for (int off = 1; off < 256; off <<= 1) {
        int x = (t >= off) ? s[t - off] : 0;
        __syncthreads();
        s[t] += x;
        __syncthreads();
    }
    if (t < NBLK) g_boff[t] = s[t] - v;
}

__global__ void block_scan_kernel() {
    __shared__ int s[256];
    int t = threadIdx.x;
    int i = blockIdx.x * 256 + t;
    int v = (i < NN) ? g_deg[i] : 0;
    s[t] = v;
    __syncthreads();
    for (int off = 1; off < 256; off <<= 1) {
        int x = (t >= off) ? s[t - off] : 0;
        __syncthreads();
        s[t] += x;
        __syncthreads();
    }
    if (i < NN) {
        int excl = s[t] - v + g_boff[blockIdx.x];
        g_off[i]  = excl;
        g_wptr[i] = excl;
    }
}

__global__ void fill_kernel(const int* __restrict__ edge_index,
                            const float* __restrict__ edge_attr) {
    int e = blockIdx.x * blockDim.x + threadIdx.x;
    if (e < NE) {
        int dst = __ldg(&edge_index[NE + e]);
        int src = __ldg(&edge_index[e]);
        float a = __ldg(&edge_attr[e]);
        int pos = atomicAdd(&g_wptr[dst], 1);
        g_edges[pos] = make_float2(__int_as_float(src), a);
    }
}

// ---------------------------------------------------------------------------
// Gather: one warp per dst node; prefetch-4 ring over packed edges.
// ---------------------------------------------------------------------------
__global__ void gather_kernel(const float* __restrict__ hidden,
                              const float* __restrict__ We,
                              const float* __restrict__ be) {
    int gtid = blockIdx.x * blockDim.x + threadIdx.x;
    int n = gtid >> 5, lane = gtid & 31;
    if (n >= NN) return;

    int deg  = g_deg[n];
    int base = g_off[n];
    int d0   = lane * 4;

    float4 w = *(const float4*)&We[d0];
    float4 b = *(const float4*)&be[d0];
    float4 acc = make_float4(0.f, 0.f, 0.f, 0.f);

    int   sbuf[4] = {0, 0, 0, 0};
    float abuf[4] = {0.f, 0.f, 0.f, 0.f};
#pragma unroll
    for (int p = 0; p < 4; p++) {
        if (p < deg) {
            float2 ed = __ldg(&g_edges[base + p]);
            sbuf[p] = __float_as_int(ed.x);
            abuf[p] = ed.y;
        }
    }

    for (int j = 0; j < deg; j++) {
        int   src = sbuf[j & 3];
        float a   = abuf[j & 3];
        float4 h  = *(const float4*)&hidden[(size_t)src * DD + d0];
        if (j + 4 < deg) {
            float2 ed = __ldg(&g_edges[base + j + 4]);
            sbuf[j & 3] = __float_as_int(ed.x);
            abuf[j & 3] = ed.y;
        }
        acc.x += fmaxf(fmaf(a, w.x, b.x) + h.x, 0.f);
        acc.y += fmaxf(fmaf(a, w.y, b.y) + h.y, 0.f);
        acc.z += fmaxf(fmaf(a, w.z, b.z) + h.z, 0.f);
        acc.w += fmaxf(fmaf(a, w.w, b.w) + h.w, 0.f);
    }

    *(float4*)&g_accum[(size_t)n * DD + d0] = acc;
    if (lane == 0) g_cnt[n] = (float)deg;
}

// ---------------------------------------------------------------------------
// GEMMs via mma.sync tf32: one 128x128x128 tile per CTA, 8 warps (4m x 2n),
// warp tile 32x64. A smem stride 132, W stride 136 => all fragment LDS
// patterns hit 32 distinct banks. FUSED finalize in A loader; bias+ReLU epi.
// ---------------------------------------------------------------------------
#define ASTR 132
#define WSTR 136
#define SMW  (128 * ASTR + 128 * WSTR + 128)   // words
#define SMB  (SMW * 4)                          // bytes = 137728

template <bool FUSED, bool RELU>
__global__ __launch_bounds__(256, 1)
void mma_gemm_kernel(const float* __restrict__ Ain,
                     const float* __restrict__ eps,
                     const float* __restrict__ W,
                     const float* __restrict__ bias,
                     float* __restrict__ C, int M) {
    extern __shared__ uint32_t smw[];
    uint32_t* As = smw;                       // [128][132] tf32 bits
    uint32_t* Ws = smw + 128 * ASTR;          // [128][136] tf32 bits
    float*    bs = (float*)(smw + 128 * ASTR + 128 * WSTR);

    const int tid  = threadIdx.x;
    const int warp = tid >> 5;
    const int lane = tid & 31;
    const int row0 = blockIdx.x * 128;
    const float s  = FUSED ? (1.f + __ldg(&eps[0])) : 0.f;

    if (tid < 128) bs[tid] = bias[tid];

    // A tile: 128 rows x 32 f4, fused finalize, tf32-round
#pragma unroll
    for (int i = 0; i < 16; i++) {
        int idx = tid + i * 256;
        int r = idx >> 5, f = idx & 31;
        int grow = row0 + r;
        float4 v = make_float4(0.f, 0.f, 0.f, 0.f);
        if (grow < M) {
            size_t off = (size_t)grow * DD + f * 4;
            v = *(const float4*)&Ain[off];
            if (FUSED) {
                float inv = 1.f / fmaxf(g_cnt[grow], 1.f);
                float4 a = *(const float4*)&g_accum[off];
                v.x = fmaf(s, v.x, a.x * inv);
                v.y = fmaf(s, v.y, a.y * inv);
                v.z = fmaf(s, v.z, a.z * inv);
                v.w = fmaf(s, v.w, a.w * inv);
            }
        }
        uint32_t* p = &As[r * ASTR + f * 4];
        p[0] = f2tf32(v.x); p[1] = f2tf32(v.y);
        p[2] = f2tf32(v.z); p[3] = f2tf32(v.w);
    }
    // W tile: 128 k-rows x 32 f4, tf32-round
#pragma unroll
    for (int i = 0; i < 16; i++) {
        int idx = tid + i * 256;
        int r = idx >> 5, f = idx & 31;
        float4 v = *(const float4*)&W[(size_t)r * DD + f * 4];
        uint32_t* p = &Ws[r * WSTR + f * 4];
        p[0] = f2tf32(v.x); p[1] = f2tf32(v.y);
        p[2] = f2tf32(v.z); p[3] = f2tf32(v.w);
    }
    __syncthreads();

    const int m0w = (warp >> 1) * 32;
    const int n0  = (warp & 1) * 64;
    const int gid = lane >> 2;
    const int tig = lane & 3;

    float acc[2][8][4];
#pragma unroll
    for (int mt = 0; mt < 2; mt++)
#pragma unroll
        for (int nt = 0; nt < 8; nt++)
#pragma unroll
            for (int c = 0; c < 4; c++) acc[mt][nt][c] = 0.f;

#pragma unroll
    for (int ks = 0; ks < 16; ks++) {
        int k0 = ks * 8;
        uint32_t a[2][4];
#pragma unroll
        for (int mt = 0; mt < 2; mt++) {
            const uint32_t* ap = &As[(m0w + mt * 16 + gid) * ASTR + k0 + tig];
            a[mt][0] = ap[0];
            a[mt][1] = ap[8 * ASTR];
            a[mt][2] = ap[4];
            a[mt][3] = ap[8 * ASTR + 4];
        }
#pragma unroll
        for (int nt = 0; nt < 8; nt++) {
            int n = n0 + nt * 8;
            uint32_t b0 = Ws[(k0 + tig) * WSTR + n + gid];
            uint32_t b1 = Ws[(k0 + tig + 4) * WSTR + n + gid];
            mma1688(acc[0][nt], a[0], b0, b1);
            mma1688(acc[1][nt], a[1], b0, b1);
        }
    }

    // epilogue: c0,c1 -> (row, col..col+1); c2,c3 -> (row+8, col..col+1)
#pragma unroll
    for (int mt = 0; mt < 2; mt++) {
        int rA = row0 + m0w + mt * 16 + gid;
        int rB = rA + 8;
#pragma unroll
        for (int nt = 0; nt < 8; nt++) {
            int colb = n0 + nt * 8 + 2 * tig;
            float bb0 = bs[colb], bb1 = bs[colb + 1];
            if (rA < M) {
                float2 o;
                o.x = acc[mt][nt][0] + bb0;
                o.y = acc[mt][nt][1] + bb1;
                if (RELU) { o.x = fmaxf(o.x, 0.f); o.y = fmaxf(o.y, 0.f); }
                *(float2*)&C[(size_t)rA * DD + colb] = o;
            }
            if (rB < M) {
                float2 o;
                o.x = acc[mt][nt][2] + bb0;
                o.y = acc[mt][nt][3] + bb1;
                if (RELU) { o.x = fmaxf(o.x, 0.f); o.y = fmaxf(o.y, 0.f); }
                *(float2*)&C[(size_t)rB * DD + colb] = o;
            }
        }
    }
}

// ---------------------------------------------------------------------------
extern "C" void kernel_launch(void* const* d_in, const int* in_sizes, int n_in,
                              void* d_out, int out_size) {
    const float* hidden = (const float*)d_in[0];
    const int*   eidx   = (const int*)d_in[1];
    const float* eattr  = (const float*)d_in[2];
    const float* We     = (const float*)d_in[3];
    const float* be     = (const float*)d_in[4];
    const float* W1     = (const float*)d_in[5];
    const float* b1     = (const float*)d_in[6];
    const float* W2     = (const float*)d_in[7];
    const float* b2     = (const float*)d_in[8];
    const float* eps    = (const float*)d_in[9];
    float*       out    = (float*)d_out;

    // DEVICE address of g_h (host &g_h is the ATS-readable shadow symbol!)
    float* p_h = nullptr;
    cudaGetSymbolAddress((void**)&p_h, g_h);

    cudaFuncSetAttribute(mma_gemm_kernel<true,  true >,
                         cudaFuncAttributeMaxDynamicSharedMemorySize, SMB);
    cudaFuncSetAttribute(mma_gemm_kernel<false, false>,
                         cudaFuncAttributeMaxDynamicSharedMemorySize, SMB);

    // --- CSR build ---
    zero_deg_kernel<<<NBLK, 256>>>();
    hist_kernel<<<(NE + 255) / 256, 256>>>(eidx);
    bsum_kernel<<<NBLK, 256>>>();
    scan_bsum_kernel<<<1, 256>>>();
    block_scan_kernel<<<NBLK, 256>>>();
    fill_kernel<<<(NE + 255) / 256, 256>>>(eidx, eattr);

    // --- gather (no float atomics) ---
    gather_kernel<<<(NN * 32 + 255) / 256, 256>>>(hidden, We, be);

    // --- MLP via tensor cores (mma.sync tf32) ---
    int gblocks = (NN + 127) / 128;   // 391
    mma_gemm_kernel<true,  true ><<<gblocks, 256, SMB>>>(hidden, eps, W1, b1, p_h, NN);
    mma_gemm_kernel<false, false><<<gblocks, 256, SMB>>>(p_h,    eps, W2, b2, out, NN);
}

// round 14
// speedup vs baseline: 1.3356x; 1.0931x over previous
#include <cuda_runtime.h>
#include <cstdint>

#define NN 50000
#define NE 800000
#define DD 128
#define NBLK 196   // ceil(50000/256)

// ------------------------- device scratch (no allocs) -----------------------
__device__ float  g_accum[NN * DD];  // aggregated messages (sum)
__device__ float  g_cnt[NN];         // in-degree (float, for GEMM1 fusion)
__device__ float  g_h[NN * DD];      // after GEMM1 + relu
__device__ int    g_deg[NN];
__device__ int    g_off[NN];         // exclusive offsets (arbitrary segment order)
__device__ int    g_wptr[NN];        // fill cursors (init = g_off)
__device__ float2 g_edges[NE];       // (src as int-bits, attr) grouped by dst
__device__ int    g_total;           // global base counter for the scan

__device__ __forceinline__ uint32_t f2tf32(float x) {
    uint32_t r;
    asm("cvt.rna.tf32.f32 %0, %1;" : "=r"(r) : "f"(x));
    return r;
}
// m16n8k8 tf32 MMA, fp32 accumulate (base PTX, sm_80+, NOT 'a'-gated)
__device__ __forceinline__ void mma1688(float* c, const uint32_t* a,
                                        uint32_t b0, uint32_t b1) {
    asm("mma.sync.aligned.m16n8k8.row.col.f32.tf32.tf32.f32 "
        "{%0,%1,%2,%3},{%4,%5,%6,%7},{%8,%9},{%0,%1,%2,%3};"
        : "+f"(c[0]), "+f"(c[1]), "+f"(c[2]), "+f"(c[3])
        : "r"(a[0]), "r"(a[1]), "r"(a[2]), "r"(a[3]), "r"(b0), "r"(b1));
}

// ---------------------------------------------------------------------------
// CSR build
// ---------------------------------------------------------------------------
__global__ void zero_deg_kernel() {
    int i = blockIdx.x * blockDim.x + threadIdx.x;
    if (i < NN) g_deg[i] = 0;
    if (i == 0) g_total = 0;
}

__global__ void hist_kernel(const int* __restrict__ edge_index) {
    int e = blockIdx.x * blockDim.x + threadIdx.x;
    if (e < NE) atomicAdd(&g_deg[__ldg(&edge_index[NE + e])], 1);
}

// single-kernel scan: block-local exclusive scan + atomic global base.
// Segment ORDER in g_edges is irrelevant (any disjoint partition works).
__global__ void scan_kernel() {
    __shared__ int s[256];
    __shared__ int base;
    int t = threadIdx.x;
    int i = blockIdx.x * 256 + t;
    int v = (i < NN) ? g_deg[i] : 0;
    s[t] = v;
    __syncthreads();
    for (int off = 1; off < 256; off <<= 1) {
        int x = (t >= off) ? s[t - off] : 0;
        __syncthreads();
        s[t] += x;
        __syncthreads();
    }
    if (t == 255) base = atomicAdd(&g_total, s[255]);
    __syncthreads();
    if (i < NN) {
        int excl = s[t] - v + base;
        g_off[i]  = excl;
        g_wptr[i] = excl;
    }
}

__global__ void fill_kernel(const int* __restrict__ edge_index,
                            const float* __restrict__ edge_attr) {
    int e = blockIdx.x * blockDim.x + threadIdx.x;
    if (e < NE) {
        int dst = __ldg(&edge_index[NE + e]);
        int src = __ldg(&edge_index[e]);
        float a = __ldg(&edge_attr[e]);
        int pos = atomicAdd(&g_wptr[dst], 1);
        g_edges[pos] = make_float2(__int_as_float(src), a);
    }
}

// ---------------------------------------------------------------------------
// Gather: one warp per dst node; prefetch-4 ring over packed edges.
// ---------------------------------------------------------------------------
__global__ void gather_kernel(const float* __restrict__ hidden,
                              const float* __restrict__ We,
                              const float* __restrict__ be) {
    int gtid = blockIdx.x * blockDim.x + threadIdx.x;
    int n = gtid >> 5, lane = gtid & 31;
    if (n >= NN) return;

    int deg  = g_deg[n];
    int base = g_off[n];
    int d0   = lane * 4;

    float4 w = *(const float4*)&We[d0];
    float4 b = *(const float4*)&be[d0];
    float4 acc = make_float4(0.f, 0.f, 0.f, 0.f);

    int   sbuf[4] = {0, 0, 0, 0};
    float abuf[4] = {0.f, 0.f, 0.f, 0.f};
#pragma unroll
    for (int p = 0; p < 4; p++) {
        if (p < deg) {
            float2 ed = __ldg(&g_edges[base + p]);
            sbuf[p] = __float_as_int(ed.x);
            abuf[p] = ed.y;
        }
    }

    for (int j = 0; j < deg; j++) {
        int   src = sbuf[j & 3];
        float a   = abuf[j & 3];
        float4 h  = *(const float4*)&hidden[(size_t)src * DD + d0];
        if (j + 4 < deg) {
            float2 ed = __ldg(&g_edges[base + j + 4]);
            sbuf[j & 3] = __float_as_int(ed.x);
            abuf[j & 3] = ed.y;
        }
        acc.x += fmaxf(fmaf(a, w.x, b.x) + h.x, 0.f);
        acc.y += fmaxf(fmaf(a, w.y, b.y) + h.y, 0.f);
        acc.z += fmaxf(fmaf(a, w.z, b.z) + h.z, 0.f);
        acc.w += fmaxf(fmaf(a, w.w, b.w) + h.w, 0.f);
    }

    *(float4*)&g_accum[(size_t)n * DD + d0] = acc;
    if (lane == 0) g_cnt[n] = (float)deg;
}

// ---------------------------------------------------------------------------
// GEMMs via mma.sync tf32: TILE_M=64 per CTA (2 CTAs/SM), 8 warps (4m x 2n),
// warp tile 16x64. A stride 132 / W stride 136 keep all fragment LDS patterns
// on 32 distinct banks. FUSED finalize in A loader; bias+ReLU epilogue.
// ---------------------------------------------------------------------------
#define ASTR 132
#define WSTR 136
#define SMW  (64 * ASTR + 128 * WSTR + 128)   // words
#define SMB  (SMW * 4)                        // bytes ~= 104 KB

template <bool FUSED, bool RELU>
__global__ __launch_bounds__(256, 2)
void mma_gemm_kernel(const float* __restrict__ Ain,
                     const float* __restrict__ eps,
                     const float* __restrict__ W,
                     const float* __restrict__ bias,
                     float* __restrict__ C, int M) {
    extern __shared__ uint32_t smw[];
    uint32_t* As = smw;                       // [64][132] tf32 bits
    uint32_t* Ws = smw + 64 * ASTR;           // [128][136] tf32 bits
    float*    bs = (float*)(smw + 64 * ASTR + 128 * WSTR);

    const int tid  = threadIdx.x;
    const int warp = tid >> 5;
    const int lane = tid & 31;
    const int row0 = blockIdx.x * 64;
    const float s  = FUSED ? (1.f + __ldg(&eps[0])) : 0.f;

    if (tid < 128) bs[tid] = bias[tid];

    // A tile: 64 rows x 32 f4, fused finalize, tf32-round
#pragma unroll
    for (int i = 0; i < 8; i++) {
        int idx = tid + i * 256;
        int r = idx >> 5, f = idx & 31;
        int grow = row0 + r;
        float4 v = make_float4(0.f, 0.f, 0.f, 0.f);
        if (grow < M) {
            size_t off = (size_t)grow * DD + f * 4;
            v = *(const float4*)&Ain[off];
            if (FUSED) {
                float inv = 1.f / fmaxf(g_cnt[grow], 1.f);
                float4 a = *(const float4*)&g_accum[off];
                v.x = fmaf(s, v.x, a.x * inv);
                v.y = fmaf(s, v.y, a.y * inv);
                v.z = fmaf(s, v.z, a.z * inv);
                v.w = fmaf(s, v.w, a.w * inv);
            }
        }
        uint32_t* p = &As[r * ASTR + f * 4];
        p[0] = f2tf32(v.x); p[1] = f2tf32(v.y);
        p[2] = f2tf32(v.z); p[3] = f2tf32(v.w);
    }
    // W tile: 128 k-rows x 32 f4, tf32-round
#pragma unroll
    for (int i = 0; i < 16; i++) {
        int idx = tid + i * 256;
        int r = idx >> 5, f = idx & 31;
        float4 v = *(const float4*)&W[(size_t)r * DD + f * 4];
        uint32_t* p = &Ws[r * WSTR + f * 4];
        p[0] = f2tf32(v.x); p[1] = f2tf32(v.y);
        p[2] = f2tf32(v.z); p[3] = f2tf32(v.w);
    }
    __syncthreads();

    const int m0w = (warp >> 1) * 16;     // 4 warps cover 64 rows
    const int n0  = (warp & 1) * 64;
    const int gid = lane >> 2;
    const int tig = lane & 3;

    float acc[8][4];
#pragma unroll
    for (int nt = 0; nt < 8; nt++)
#pragma unroll
        for (int c = 0; c < 4; c++) acc[nt][c] = 0.f;

#pragma unroll
    for (int ks = 0; ks < 16; ks++) {
        int k0 = ks * 8;
        uint32_t a[4];
        {
            const uint32_t* ap = &As[(m0w + gid) * ASTR + k0 + tig];
            a[0] = ap[0];
            a[1] = ap[8 * ASTR];
            a[2] = ap[4];
            a[3] = ap[8 * ASTR + 4];
        }
#pragma unroll
        for (int nt = 0; nt < 8; nt++) {
            int n = n0 + nt * 8;
            uint32_t b0 = Ws[(k0 + tig) * WSTR + n + gid];
            uint32_t b1 = Ws[(k0 + tig + 4) * WSTR + n + gid];
            mma1688(acc[nt], a, b0, b1);
        }
    }

    // epilogue: c0,c1 -> (row, col..col+1); c2,c3 -> (row+8, col..col+1)
    int rA = row0 + m0w + gid;
    int rB = rA + 8;
#pragma unroll
    for (int nt = 0; nt < 8; nt++) {
        int colb = n0 + nt * 8 + 2 * tig;
        float bb0 = bs[colb], bb1 = bs[colb + 1];
        if (rA < M) {
            float2 o;
            o.x = acc[nt][0] + bb0;
            o.y = acc[nt][1] + bb1;
            if (RELU) { o.x = fmaxf(o.x, 0.f); o.y = fmaxf(o.y, 0.f); }
            *(float2*)&C[(size_t)rA * DD + colb] = o;
        }
        if (rB < M) {
            float2 o;
            o.x = acc[nt][2] + bb0;
            o.y = acc[nt][3] + bb1;
            if (RELU) { o.x = fmaxf(o.x, 0.f); o.y = fmaxf(o.y, 0.f); }
            *(float2*)&C[(size_t)rB * DD + colb] = o;
        }
    }
}

// ---------------------------------------------------------------------------
extern "C" void kernel_launch(void* const* d_in, const int* in_sizes, int n_in,
                              void* d_out, int out_size) {
    const float* hidden = (const float*)d_in[0];
    const int*   eidx   = (const int*)d_in[1];
    const float* eattr  = (const float*)d_in[2];
    const float* We     = (const float*)d_in[3];
    const float* be     = (const float*)d_in[4];
    const float* W1     = (const float*)d_in[5];
    const float* b1     = (const float*)d_in[6];
    const float* W2     = (const float*)d_in[7];
    const float* b2     = (const float*)d_in[8];
    const float* eps    = (const float*)d_in[9];
    float*       out    = (float*)d_out;

    // DEVICE address of g_h (host &g_h is the ATS-readable shadow symbol!)
    float* p_h = nullptr;
    cudaGetSymbolAddress((void**)&p_h, g_h);

    cudaFuncSetAttribute(mma_gemm_kernel<true,  true >,
                         cudaFuncAttributeMaxDynamicSharedMemorySize, SMB);
    cudaFuncSetAttribute(mma_gemm_kernel<false, false>,
                         cudaFuncAttributeMaxDynamicSharedMemorySize, SMB);

    // --- CSR build ---
    zero_deg_kernel<<<NBLK, 256>>>();
    hist_kernel<<<(NE + 255) / 256, 256>>>(eidx);
    scan_kernel<<<NBLK, 256>>>();
    fill_kernel<<<(NE + 255) / 256, 256>>>(eidx, eattr);

    // --- gather (no float atomics) ---
    gather_kernel<<<(NN * 32 + 255) / 256, 256>>>(hidden, We, be);

    // --- MLP via tensor cores (mma.sync tf32) ---
    int gblocks = (NN + 63) / 64;   // 782
    mma_gemm_kernel<true,  true ><<<gblocks, 256, SMB>>>(hidden, eps, W1, b1, p_h, NN);
    mma_gemm_kernel<false, false><<<gblocks, 256, SMB>>>(p_h,    eps, W2, b2, out, NN);
}

// round 15
// speedup vs baseline: 1.3544x; 1.0141x over previous
#include <cuda_runtime.h>
#include <cstdint>

#define NN 50000
#define NE 800000
#define DD 128
#define NBLK 196   // ceil(50000/256)

// ------------------------- device scratch (no allocs) -----------------------
__device__ float  g_accum[NN * DD];  // aggregated messages (sum)
__device__ float  g_cnt[NN];         // in-degree (float, for GEMM1 fusion)
__device__ float  g_h[NN * DD];      // after GEMM1 + relu
__device__ int    g_deg[NN];
__device__ int    g_off[NN];         // exclusive offsets (arbitrary segment order)
__device__ int    g_wptr[NN];        // fill cursors (init = g_off)
__device__ float2 g_edges[NE];       // (src as int-bits, attr) grouped by dst
__device__ int    g_total;           // global base counter for the scan

__device__ __forceinline__ uint32_t f2tf32(float x) {
    uint32_t r;
    asm("cvt.rna.tf32.f32 %0, %1;" : "=r"(r) : "f"(x));
    return r;
}
// m16n8k8 tf32 MMA, fp32 accumulate (base PTX, sm_80+, NOT 'a'-gated)
__device__ __forceinline__ void mma1688(float* c, const uint32_t* a,
                                        uint32_t b0, uint32_t b1) {
    asm("mma.sync.aligned.m16n8k8.row.col.f32.tf32.tf32.f32 "
        "{%0,%1,%2,%3},{%4,%5,%6,%7},{%8,%9},{%0,%1,%2,%3};"
        : "+f"(c[0]), "+f"(c[1]), "+f"(c[2]), "+f"(c[3])
        : "r"(a[0]), "r"(a[1]), "r"(a[2]), "r"(a[3]), "r"(b0), "r"(b1));
}

// ---------------------------------------------------------------------------
// CSR build
// ---------------------------------------------------------------------------
__global__ void zero_deg_kernel() {
    int i = blockIdx.x * blockDim.x + threadIdx.x;
    if (i < NN) g_deg[i] = 0;
    if (i == 0) g_total = 0;
}

// 4 edges per thread, vectorized index load
__global__ void hist_kernel(const int* __restrict__ edge_index) {
    int q = blockIdx.x * blockDim.x + threadIdx.x;   // quad id
    if (q * 4 >= NE) return;
    int4 d = *(const int4*)&edge_index[NE + q * 4];
    atomicAdd(&g_deg[d.x], 1);
    atomicAdd(&g_deg[d.y], 1);
    atomicAdd(&g_deg[d.z], 1);
    atomicAdd(&g_deg[d.w], 1);
}

// single-kernel scan: block-local exclusive scan + atomic global base.
// Segment ORDER in g_edges is irrelevant (any disjoint partition works).
__global__ void scan_kernel() {
    __shared__ int s[256];
    __shared__ int base;
    int t = threadIdx.x;
    int i = blockIdx.x * 256 + t;
    int v = (i < NN) ? g_deg[i] : 0;
    s[t] = v;
    __syncthreads();
    for (int off = 1; off < 256; off <<= 1) {
        int x = (t >= off) ? s[t - off] : 0;
        __syncthreads();
        s[t] += x;
        __syncthreads();
    }
    if (t == 255) base = atomicAdd(&g_total, s[255]);
    __syncthreads();
    if (i < NN) {
        int excl = s[t] - v + base;
        g_off[i]  = excl;
        g_wptr[i] = excl;
    }
}

// 4 edges per thread, vectorized loads
__global__ void fill_kernel(const int* __restrict__ edge_index,
                            const float* __restrict__ edge_attr) {
    int q = blockIdx.x * blockDim.x + threadIdx.x;
    if (q * 4 >= NE) return;
    int4   sv = *(const int4*)&edge_index[q * 4];
    int4   dv = *(const int4*)&edge_index[NE + q * 4];
    float4 av = *(const float4*)&edge_attr[q * 4];

    int p0 = atomicAdd(&g_wptr[dv.x], 1);
    int p1 = atomicAdd(&g_wptr[dv.y], 1);
    int p2 = atomicAdd(&g_wptr[dv.z], 1);
    int p3 = atomicAdd(&g_wptr[dv.w], 1);
    g_edges[p0] = make_float2(__int_as_float(sv.x), av.x);
    g_edges[p1] = make_float2(__int_as_float(sv.y), av.y);
    g_edges[p2] = make_float2(__int_as_float(sv.z), av.z);
    g_edges[p3] = make_float2(__int_as_float(sv.w), av.w);
}

// ---------------------------------------------------------------------------
// Gather: one warp per dst node; prefetch-4 ring over packed edges.
// ---------------------------------------------------------------------------
__global__ void gather_kernel(const float* __restrict__ hidden,
                              const float* __restrict__ We,
                              const float* __restrict__ be) {
    int gtid = blockIdx.x * blockDim.x + threadIdx.x;
    int n = gtid >> 5, lane = gtid & 31;
    if (n >= NN) return;

    int deg  = g_deg[n];
    int base = g_off[n];
    int d0   = lane * 4;

    float4 w = *(const float4*)&We[d0];
    float4 b = *(const float4*)&be[d0];
    float4 acc = make_float4(0.f, 0.f, 0.f, 0.f);

    int   sbuf[4] = {0, 0, 0, 0};
    float abuf[4] = {0.f, 0.f, 0.f, 0.f};
#pragma unroll
    for (int p = 0; p < 4; p++) {
        if (p < deg) {
            float2 ed = __ldg(&g_edges[base + p]);
            sbuf[p] = __float_as_int(ed.x);
            abuf[p] = ed.y;
        }
    }

    for (int j = 0; j < deg; j++) {
        int   src = sbuf[j & 3];
        float a   = abuf[j & 3];
        float4 h  = *(const float4*)&hidden[(size_t)src * DD + d0];
        if (j + 4 < deg) {
            float2 ed = __ldg(&g_edges[base + j + 4]);
            sbuf[j & 3] = __float_as_int(ed.x);
            abuf[j & 3] = ed.y;
        }
        acc.x += fmaxf(fmaf(a, w.x, b.x) + h.x, 0.f);
        acc.y += fmaxf(fmaf(a, w.y, b.y) + h.y, 0.f);
        acc.z += fmaxf(fmaf(a, w.z, b.z) + h.z, 0.f);
        acc.w += fmaxf(fmaf(a, w.w, b.w) + h.w, 0.f);
    }

    *(float4*)&g_accum[(size_t)n * DD + d0] = acc;
    if (lane == 0) g_cnt[n] = (float)deg;
}

// ---------------------------------------------------------------------------
// PERSISTENT GEMMs via mma.sync tf32: grid=296 (2 CTAs/SM). Each CTA loads
// W once, then loops over 64-row tiles. 8 warps (4m x 2n), warp tile 16x64.
// A stride 132 / W stride 136: conflict-free fragment LDS. FUSED finalize.
// ---------------------------------------------------------------------------
#define ASTR 132
#define WSTR 136
#define SMW  (64 * ASTR + 128 * WSTR + 128)   // words
#define SMB  (SMW * 4)                        // ~104 KB
#define NTILES ((NN + 63) / 64)               // 782
#define GGRID 296

template <bool FUSED, bool RELU>
__global__ __launch_bounds__(256, 2)
void mma_gemm_kernel(const float* __restrict__ Ain,
                     const float* __restrict__ eps,
                     const float* __restrict__ W,
                     const float* __restrict__ bias,
                     float* __restrict__ C, int M) {
    extern __shared__ uint32_t smw[];
    uint32_t* As = smw;                       // [64][132] tf32 bits
    uint32_t* Ws = smw + 64 * ASTR;           // [128][136] tf32 bits
    float*    bs = (float*)(smw + 64 * ASTR + 128 * WSTR);

    const int tid  = threadIdx.x;
    const int warp = tid >> 5;
    const int lane = tid & 31;
    const float s  = FUSED ? (1.f + __ldg(&eps[0])) : 0.f;

    if (tid < 128) bs[tid] = bias[tid];

    // W tile: loaded ONCE per CTA: 128 k-rows x 32 f4, tf32-round
#pragma unroll
    for (int i = 0; i < 16; i++) {
        int idx = tid + i * 256;
        int r = idx >> 5, f = idx & 31;
        float4 v = *(const float4*)&W[(size_t)r * DD + f * 4];
        uint32_t* p = &Ws[r * WSTR + f * 4];
        p[0] = f2tf32(v.x); p[1] = f2tf32(v.y);
        p[2] = f2tf32(v.z); p[3] = f2tf32(v.w);
    }

    const int m0w = (warp >> 1) * 16;
    const int n0  = (warp & 1) * 64;
    const int gid = lane >> 2;
    const int tig = lane & 3;

    for (int tile = blockIdx.x; tile < NTILES; tile += GGRID) {
        int row0 = tile * 64;

        __syncthreads();   // previous iteration's MMA reads of As complete
        // A tile: 64 rows x 32 f4, fused finalize, tf32-round
#pragma unroll
        for (int i = 0; i < 8; i++) {
            int idx = tid + i * 256;
            int r = idx >> 5, f = idx & 31;
            int grow = row0 + r;
            float4 v = make_float4(0.f, 0.f, 0.f, 0.f);
            if (grow < M) {
                size_t off = (size_t)grow * DD + f * 4;
                v = *(const float4*)&Ain[off];
                if (FUSED) {
                    float inv = 1.f / fmaxf(g_cnt[grow], 1.f);
                    float4 a = *(const float4*)&g_accum[off];
                    v.x = fmaf(s, v.x, a.x * inv);
                    v.y = fmaf(s, v.y, a.y * inv);
                    v.z = fmaf(s, v.z, a.z * inv);
                    v.w = fmaf(s, v.w, a.w * inv);
                }
            }
            uint32_t* p = &As[r * ASTR + f * 4];
            p[0] = f2tf32(v.x); p[1] = f2tf32(v.y);
            p[2] = f2tf32(v.z); p[3] = f2tf32(v.w);
        }
        __syncthreads();

        float acc[8][4];
#pragma unroll
        for (int nt = 0; nt < 8; nt++)
#pragma unroll
            for (int c = 0; c < 4; c++) acc[nt][c] = 0.f;

#pragma unroll
        for (int ks = 0; ks < 16; ks++) {
            int k0 = ks * 8;
            uint32_t a[4];
            {
                const uint32_t* ap = &As[(m0w + gid) * ASTR + k0 + tig];
                a[0] = ap[0];
                a[1] = ap[8 * ASTR];
                a[2] = ap[4];
                a[3] = ap[8 * ASTR + 4];
            }
#pragma unroll
            for (int nt = 0; nt < 8; nt++) {
                int n = n0 + nt * 8;
                uint32_t b0 = Ws[(k0 + tig) * WSTR + n + gid];
                uint32_t b1 = Ws[(k0 + tig + 4) * WSTR + n + gid];
                mma1688(acc[nt], a, b0, b1);
            }
        }

        // epilogue
        int rA = row0 + m0w + gid;
        int rB = rA + 8;
#pragma unroll
        for (int nt = 0; nt < 8; nt++) {
            int colb = n0 + nt * 8 + 2 * tig;
            float bb0 = bs[colb], bb1 = bs[colb + 1];
            if (rA < M) {
                float2 o;
                o.x = acc[nt][0] + bb0;
                o.y = acc[nt][1] + bb1;
                if (RELU) { o.x = fmaxf(o.x, 0.f); o.y = fmaxf(o.y, 0.f); }
                *(float2*)&C[(size_t)rA * DD + colb] = o;
            }
            if (rB < M) {
                float2 o;
                o.x = acc[nt][2] + bb0;
                o.y = acc[nt][3] + bb1;
                if (RELU) { o.x = fmaxf(o.x, 0.f); o.y = fmaxf(o.y, 0.f); }
                *(float2*)&C[(size_t)rB * DD + colb] = o;
            }
        }
    }
}

// ---------------------------------------------------------------------------
extern "C" void kernel_launch(void* const* d_in, const int* in_sizes, int n_in,
                              void* d_out, int out_size) {
    const float* hidden = (const float*)d_in[0];
    const int*   eidx   = (const int*)d_in[1];
    const float* eattr  = (const float*)d_in[2];
    const float* We     = (const float*)d_in[3];
    const float* be     = (const float*)d_in[4];
    const float* W1     = (const float*)d_in[5];
    const float* b1     = (const float*)d_in[6];
    const float* W2     = (const float*)d_in[7];
    const float* b2     = (const float*)d_in[8];
    const float* eps    = (const float*)d_in[9];
    float*       out    = (float*)d_out;

    // DEVICE address of g_h (host &g_h is the ATS-readable shadow symbol!)
    float* p_h = nullptr;
    cudaGetSymbolAddress((void**)&p_h, g_h);

    cudaFuncSetAttribute(mma_gemm_kernel<true,  true >,
                         cudaFuncAttributeMaxDynamicSharedMemorySize, SMB);
    cudaFuncSetAttribute(mma_gemm_kernel<false, false>,
                         cudaFuncAttributeMaxDynamicSharedMemorySize, SMB);

    // --- CSR build ---
    zero_deg_kernel<<<NBLK, 256>>>();
    hist_kernel<<<(NE / 4 + 255) / 256, 256>>>(eidx);
    scan_kernel<<<NBLK, 256>>>();
    fill_kernel<<<(NE / 4 + 255) / 256, 256>>>(eidx, eattr);

    // --- gather (no float atomics) ---
    gather_kernel<<<(NN * 32 + 255) / 256, 256>>>(hidden, We, be);

    // --- MLP via tensor cores (persistent mma.sync tf32) ---
    mma_gemm_kernel<true,  true ><<<GGRID, 256, SMB>>>(hidden, eps, W1, b1, p_h, NN);
    mma_gemm_kernel<false, false><<<GGRID, 256, SMB>>>(p_h,    eps, W2, b2, out, NN);
}